// round 1
// baseline (speedup 1.0000x reference)
#include <cuda_runtime.h>
#include <math.h>

#define N_ROWS  131072
#define S_DIM   64
#define H_DIM   128
#define K_CODES 512
#define A_DIM   8

#define TM       128     // rows per CTA
#define KT       128     // codes per score tile
#define NTHREADS 256

// Precomputed per-code data (written by precompute_kernel each launch)
__device__ float g_ee[K_CODES];            // sum(e*e) per code (fp64-accurate)
__device__ float g_probs[K_CODES * A_DIM]; // softmax(e@Wa+ba)
__device__ float g_value[K_CODES];         // e@Wv+bv

// ---------------------------------------------------------------------------
// Kernel 1: per-code table. 512 threads total.
// ---------------------------------------------------------------------------
__global__ void precompute_kernel(const float* __restrict__ emb,
                                  const float* __restrict__ Wa,
                                  const float* __restrict__ ba,
                                  const float* __restrict__ Wv,
                                  const float* __restrict__ bv)
{
    int k = blockIdx.x * blockDim.x + threadIdx.x;
    if (k >= K_CODES) return;
    const float* e = emb + k * H_DIM;

    double ee = 0.0;
    float logit[A_DIM];
#pragma unroll
    for (int a = 0; a < A_DIM; a++) logit[a] = 0.0f;
    float val = 0.0f;

    for (int j = 0; j < H_DIM; j++) {
        float ej = e[j];
        ee += (double)ej * (double)ej;
#pragma unroll
        for (int a = 0; a < A_DIM; a++)
            logit[a] = fmaf(ej, Wa[j * A_DIM + a], logit[a]);
        val = fmaf(ej, Wv[j], val);
    }
#pragma unroll
    for (int a = 0; a < A_DIM; a++) logit[a] += ba[a];
    val += bv[0];

    g_ee[k] = (float)ee;
    g_value[k] = val;

    // softmax (temperature = 1.0)
    float m = logit[0];
#pragma unroll
    for (int a = 1; a < A_DIM; a++) m = fmaxf(m, logit[a]);
    float p[A_DIM];
    float s = 0.0f;
#pragma unroll
    for (int a = 0; a < A_DIM; a++) { p[a] = expf(logit[a] - m); s += p[a]; }
#pragma unroll
    for (int a = 0; a < A_DIM; a++) g_probs[k * A_DIM + a] = p[a] / s;
}

// ---------------------------------------------------------------------------
// Kernel 2: fused encoder + VQ argmin + table lookup.
// SMEM layout (floats):
//   [0      .. 16384) sX1T : x1 transposed [H][TM]; later vv[128] + reduction
//   [16384  .. 32768) sX2T : x2 transposed [H][TM]
//   [32768  .. 49664) sBig : stage1 {sInT[64][128], sW1[64][128]},
//                            stage2 Wh[128][128], stage3 ET[128][132]
// ---------------------------------------------------------------------------
#define SMEM_FLOATS (32768 + 128 * 132)
#define SMEM_BYTES  (SMEM_FLOATS * 4)

__global__ __launch_bounds__(NTHREADS, 1)
void fused_kernel(const float* __restrict__ in,
                  const float* __restrict__ W1, const float* __restrict__ b1,
                  const float* __restrict__ Wh, const float* __restrict__ bh,
                  const float* __restrict__ emb,
                  float* __restrict__ out)
{
    extern __shared__ float sm[];
    float* sX1T = sm;
    float* sX2T = sm + 16384;
    float* sBig = sm + 32768;
    float* sInT = sBig;          // [64][128]
    float* sW1  = sBig + 8192;   // [64][128]
    float* sWh  = sBig;          // [128][128]
    float* sET  = sBig;          // [128][132] (pitch 132 keeps 16B alignment)

    const int tid = threadIdx.x;
    const int tx = tid & 15, ty = tid >> 4;
    const int c0 = tx * 8, r0 = ty * 8;
    const int rowBase = blockIdx.x * TM;

    // ---------------- Stage 0: load inputs (transposed) + W1 ----------------
    {
        const float4* gin = (const float4*)(in + (size_t)rowBase * S_DIM);
#pragma unroll
        for (int f = tid; f < TM * S_DIM / 4; f += NTHREADS) {  // 2048
            float4 v = gin[f];
            int row = f >> 4;          // (f*4)/64
            int s   = (f & 15) * 4;
            sInT[(s + 0) * TM + row] = v.x;
            sInT[(s + 1) * TM + row] = v.y;
            sInT[(s + 2) * TM + row] = v.z;
            sInT[(s + 3) * TM + row] = v.w;
        }
        const float4* gW1 = (const float4*)W1;
#pragma unroll
        for (int f = tid; f < S_DIM * H_DIM / 4; f += NTHREADS) // 2048
            ((float4*)sW1)[f] = gW1[f];
    }
    __syncthreads();

    // ---------------- Stage 1: x1 = relu(in@W1 + b1) ----------------
    {
        float acc[8][8];
#pragma unroll
        for (int i = 0; i < 8; i++)
#pragma unroll
            for (int j = 0; j < 8; j++) acc[i][j] = 0.0f;

#pragma unroll 4
        for (int d = 0; d < S_DIM; d++) {
            float4 a0 = *(const float4*)(sInT + d * TM + r0);
            float4 a1 = *(const float4*)(sInT + d * TM + r0 + 4);
            float4 bb0 = *(const float4*)(sW1 + d * H_DIM + c0);
            float4 bb1 = *(const float4*)(sW1 + d * H_DIM + c0 + 4);
            float av[8] = {a0.x, a0.y, a0.z, a0.w, a1.x, a1.y, a1.z, a1.w};
            float bv_[8] = {bb0.x, bb0.y, bb0.z, bb0.w, bb1.x, bb1.y, bb1.z, bb1.w};
#pragma unroll
            for (int i = 0; i < 8; i++)
#pragma unroll
                for (int j = 0; j < 8; j++)
                    acc[i][j] = fmaf(av[i], bv_[j], acc[i][j]);
        }
#pragma unroll
        for (int j = 0; j < 8; j++) {
            float bj = b1[c0 + j];
#pragma unroll
            for (int i = 0; i < 8; i++)
                sX1T[(c0 + j) * TM + (r0 + i)] = fmaxf(acc[i][j] + bj, 0.0f);
        }
    }
    __syncthreads();

    // ---------------- Load Wh (overwrites sInT/sW1) ----------------
    {
        const float4* gWh = (const float4*)Wh;
#pragma unroll
        for (int f = tid; f < H_DIM * H_DIM / 4; f += NTHREADS)  // 4096
            ((float4*)sWh)[f] = gWh[f];
    }
    __syncthreads();

    // ---------------- Stage 2: x2 = relu(x1@Wh + bh) ----------------
    {
        float acc[8][8];
#pragma unroll
        for (int i = 0; i < 8; i++)
#pragma unroll
            for (int j = 0; j < 8; j++) acc[i][j] = 0.0f;

#pragma unroll 4
        for (int d = 0; d < H_DIM; d++) {
            float4 a0 = *(const float4*)(sX1T + d * TM + r0);
            float4 a1 = *(const float4*)(sX1T + d * TM + r0 + 4);
            float4 bb0 = *(const float4*)(sWh + d * H_DIM + c0);
            float4 bb1 = *(const float4*)(sWh + d * H_DIM + c0 + 4);
            float av[8] = {a0.x, a0.y, a0.z, a0.w, a1.x, a1.y, a1.z, a1.w};
            float bv_[8] = {bb0.x, bb0.y, bb0.z, bb0.w, bb1.x, bb1.y, bb1.z, bb1.w};
#pragma unroll
            for (int i = 0; i < 8; i++)
#pragma unroll
                for (int j = 0; j < 8; j++)
                    acc[i][j] = fmaf(av[i], bv_[j], acc[i][j]);
        }
#pragma unroll
        for (int j = 0; j < 8; j++) {
            float bj = bh[c0 + j];
#pragma unroll
            for (int i = 0; i < 8; i++)
                sX2T[(c0 + j) * TM + (r0 + i)] = fmaxf(acc[i][j] + bj, 0.0f);
        }
    }
    __syncthreads();

    // ---------------- vv = ||x||^2 per row (sX1T now free) ----------------
    float* vv = sX1T;  // [128]
    if (tid < TM) {
        float s = 0.0f;
#pragma unroll 4
        for (int d = 0; d < H_DIM; d++) {
            float x = sX2T[d * TM + tid];
            s = fmaf(x, x, s);
        }
        vv[tid] = s;
    }
    __syncthreads();

    float vvr[8];
#pragma unroll
    for (int i = 0; i < 8; i++) vvr[i] = vv[r0 + i];

    float bestD[8];
    int bestI[8];
#pragma unroll
    for (int i = 0; i < 8; i++) { bestD[i] = __int_as_float(0x7f800000); bestI[i] = 0; }

    // ---------------- Stage 3: scores vs all 512 codes, 4 tiles ----------------
    for (int tile = 0; tile < K_CODES / KT; tile++) {
        // load E tile transposed into sET [d][code], pitch 132
        const float4* ge = (const float4*)(emb + (size_t)tile * KT * H_DIM);
#pragma unroll
        for (int f = tid; f < KT * H_DIM / 4; f += NTHREADS) {  // 4096
            float4 v = ge[f];
            int code = f >> 5;         // (f*4)/128
            int d    = (f & 31) * 4;
            sET[(d + 0) * 132 + code] = v.x;
            sET[(d + 1) * 132 + code] = v.y;
            sET[(d + 2) * 132 + code] = v.z;
            sET[(d + 3) * 132 + code] = v.w;
        }
        __syncthreads();

        float acc[8][8];
#pragma unroll
        for (int i = 0; i < 8; i++)
#pragma unroll
            for (int j = 0; j < 8; j++) acc[i][j] = 0.0f;

#pragma unroll 4
        for (int d = 0; d < H_DIM; d++) {
            float4 a0 = *(const float4*)(sX2T + d * TM + r0);
            float4 a1 = *(const float4*)(sX2T + d * TM + r0 + 4);
            float4 bb0 = *(const float4*)(sET + d * 132 + c0);
            float4 bb1 = *(const float4*)(sET + d * 132 + c0 + 4);
            float av[8] = {a0.x, a0.y, a0.z, a0.w, a1.x, a1.y, a1.z, a1.w};
            float bv_[8] = {bb0.x, bb0.y, bb0.z, bb0.w, bb1.x, bb1.y, bb1.z, bb1.w};
#pragma unroll
            for (int i = 0; i < 8; i++)
#pragma unroll
                for (int j = 0; j < 8; j++)
                    acc[i][j] = fmaf(av[i], bv_[j], acc[i][j]);
        }

        int codeBase = tile * KT + c0;
#pragma unroll
        for (int j = 0; j < 8; j++) {
            float ee = g_ee[codeBase + j];
#pragma unroll
            for (int i = 0; i < 8; i++) {
                // faithful to reference: d = (vv - 2*dot) + ee, no FMA fusion
                float dd = __fadd_rn(__fsub_rn(vvr[i], __fmul_rn(2.0f, acc[i][j])), ee);
                if (dd < bestD[i]) { bestD[i] = dd; bestI[i] = codeBase + j; }
            }
        }
        __syncthreads();
    }

    // ---------------- Cross-thread argmin reduction + output ----------------
    float* redD = sX1T + 128;                 // [128][16]
    int*   redI = (int*)(sX1T + 128 + TM * 16);
#pragma unroll
    for (int i = 0; i < 8; i++) {
        redD[(r0 + i) * 16 + tx] = bestD[i];
        redI[(r0 + i) * 16 + tx] = bestI[i];
    }
    __syncthreads();

    if (tid < TM) {
        float best = redD[tid * 16];
        int bi = redI[tid * 16];
#pragma unroll
        for (int t = 1; t < 16; t++) {
            float v = redD[tid * 16 + t];
            int id = redI[tid * 16 + t];
            if (v < best || (v == best && id < bi)) { best = v; bi = id; }
        }
        int gr = rowBase + tid;
        float4 p0 = *(const float4*)(g_probs + bi * A_DIM);
        float4 p1 = *(const float4*)(g_probs + bi * A_DIM + 4);
        float4* po = (float4*)out;
        po[gr * 2 + 0] = p0;
        po[gr * 2 + 1] = p1;
        out[(size_t)N_ROWS * A_DIM + gr] = g_value[bi];
    }
}

// ---------------------------------------------------------------------------
extern "C" void kernel_launch(void* const* d_in, const int* in_sizes, int n_in,
                              void* d_out, int out_size)
{
    const float* inputs = (const float*)d_in[0];
    const float* W1  = (const float*)d_in[1];
    const float* b1  = (const float*)d_in[2];
    const float* Wh  = (const float*)d_in[3];
    const float* bh  = (const float*)d_in[4];
    const float* emb = (const float*)d_in[5];
    const float* Wa  = (const float*)d_in[6];
    const float* ba  = (const float*)d_in[7];
    const float* Wv  = (const float*)d_in[8];
    const float* bv  = (const float*)d_in[9];

    cudaFuncSetAttribute(fused_kernel,
                         cudaFuncAttributeMaxDynamicSharedMemorySize, SMEM_BYTES);

    precompute_kernel<<<2, 256>>>(emb, Wa, ba, Wv, bv);
    fused_kernel<<<N_ROWS / TM, NTHREADS, SMEM_BYTES>>>(
        inputs, W1, b1, Wh, bh, emb, (float*)d_out);
}